// round 13
// baseline (speedup 1.0000x reference)
#include <cuda_runtime.h>

// CANN recurrent net, 14 PDL-chained graph nodes, fence-free token dataflow.
//   step t: y = J @ s_{t-1};  U = y/recSum_{t-1} + Iext;  s_t = (0.2 U)^2
//   step 14 additionally feeds a 149th collector CTA -> recSum_14, r_14.
//
// PDL is used ONLY to launch successor CTAs early (gate opens right after the
// predecessor issues its J prefetch). Consumers do NOT call griddepcontrol.wait;
// they poll per-row 64-bit tokens {tag|s-bits} in L2 (value rides with the tag,
// so no fence/flush is needed) and scatter to smem as rows arrive. The serial
// step-to-step path is: last row publish -> one poll round -> matvec -> publish.
//
// Replay-safe tags: per-step counters; every CTA of execution r computes
// r = atomicAdd(cnt,1)/gridDim, uniform within the execution. Token tag = r+1.

#define Nn     1680
#define NBLK   148
#define TPB    384          // 12 warps, 1 warp = 1 row (12*148 = 1776 slots)
#define ITERS  14
#define KC     0.005f

__device__ unsigned long long g_tok[ITERS + 1][Nn];  // per-step tokens {tag|s}
__device__ unsigned           g_cnt[ITERS + 1];      // per-step execution counters

__device__ __forceinline__ void pdl_launch_dependents() {
    asm volatile("griddepcontrol.launch_dependents;" ::: "memory");
}
__device__ __forceinline__ unsigned long long ldcg64(const unsigned long long* p) {
    unsigned long long v;
    asm volatile("ld.global.cg.u64 %0, [%1];" : "=l"(v) : "l"(p));
    return v;
}
__device__ __forceinline__ void stcg64(unsigned long long* p, unsigned long long v) {
    asm volatile("st.global.cg.u64 [%0], %1;" :: "l"(p), "l"(v) : "memory");
}

// Poll slots tid + k*TPB (k=0..4; tid<144 own 5) of g_tok[src] for tag,
// scattering payloads into s_sm. Returns per-thread fixed-order value sum.
__device__ __forceinline__ float poll_scatter(int src, unsigned tag, int tid,
                                              float* s_sm) {
    const unsigned long long* slots = g_tok[src];
    const int cnt = (tid < Nn - 4 * TPB) ? 5 : 4;
    const unsigned need = (1u << cnt) - 1u;
    float vals[5] = {0.f, 0.f, 0.f, 0.f, 0.f};
    unsigned done = 0;
    while (done != need) {
        unsigned long long v[5];
        const unsigned pend = need & ~done;
        #pragma unroll
        for (int k = 0; k < 5; ++k)
            if (pend & (1u << k)) v[k] = ldcg64(&slots[tid + k * TPB]);
        #pragma unroll
        for (int k = 0; k < 5; ++k)
            if ((pend & (1u << k)) && (unsigned)(v[k] >> 32) == tag) {
                float f = __uint_as_float((unsigned)v[k]);
                vals[k] = f;
                s_sm[tid + k * TPB] = f;
                done |= 1u << k;
            }
    }
    return ((vals[0] + vals[1]) + (vals[2] + vals[3])) + vals[4];
}

// Worker body for step t (grid_div = gridDim.x of this kernel, for run id).
__device__ __forceinline__ void step_body(const float* __restrict__ net_in,
                                          const float* __restrict__ J,
                                          float* __restrict__ out,
                                          int t, unsigned grid_div)
{
    __shared__ __align__(16) float s_sm[Nn];
    __shared__ unsigned s_run;

    const int tid  = threadIdx.x;
    const int lane = tid & 31;
    const int wid  = tid >> 5;
    const int row  = wid * NBLK + (int)blockIdx.x;
    const bool active = (row < Nn);

    if (tid == 0) s_run = atomicAdd(&g_cnt[t], 1u) / grid_div;

    // ---- prefetch (input-independent): J row -> regs, Iext ----
    float4 Jr[13];
    float jtail = 0.f, iext = 0.f;
    if (active) {
        iext = __ldg(&net_in[row]);
        const float* Jrow = J + (size_t)row * Nn;
        const float4* Jp = reinterpret_cast<const float4*>(Jrow);
        #pragma unroll
        for (int j = 0; j < 13; ++j) Jr[j] = __ldg(&Jp[j * 32 + lane]);
        if (lane < 16) jtail = __ldg(&Jrow[1664 + lane]);
    }

    if (t == 1) {   // launch-constant input
        const float4* r4 = reinterpret_cast<const float4*>(net_in + Nn);
        #pragma unroll
        for (int k = 0; k < 2; ++k) {
            int i = tid + k * TPB;
            if (i < Nn / 4) reinterpret_cast<float4*>(s_sm)[i] = __ldg(&r4[i]);
        }
    }

    pdl_launch_dependents();   // successor CTAs become resident + start polling
    __syncthreads();           // s_run visible (and t=1 staging complete)
    const unsigned run = s_run;

    if (t != 1)
        (void)poll_scatter(t - 1, run + 1u, tid, s_sm);
    __syncthreads();

    // ---- matvec with fused recSum (each warp covers all of s) ----
    if (active) {
        const float4* s4 = reinterpret_cast<const float4*>(s_sm);
        float a0 = 0.f, a1 = 0.f, rs = 0.f;
        #pragma unroll
        for (int j = 0; j < 13; ++j) {
            float4 b = s4[j * 32 + lane];
            rs += (b.x + b.y) + (b.z + b.w);
            if (j & 1) {
                a1 = fmaf(Jr[j].x, b.x, a1); a1 = fmaf(Jr[j].y, b.y, a1);
                a1 = fmaf(Jr[j].z, b.z, a1); a1 = fmaf(Jr[j].w, b.w, a1);
            } else {
                a0 = fmaf(Jr[j].x, b.x, a0); a0 = fmaf(Jr[j].y, b.y, a0);
                a0 = fmaf(Jr[j].z, b.z, a0); a0 = fmaf(Jr[j].w, b.w, a0);
            }
        }
        if (lane < 16) {
            float bt = s_sm[1664 + lane];
            rs += bt;
            a1 = fmaf(jtail, bt, a1);
        }
        float acc = a0 + a1;
        #pragma unroll
        for (int o = 16; o; o >>= 1) {
            acc += __shfl_xor_sync(0xffffffffu, acc, o);
            rs  += __shfl_xor_sync(0xffffffffu, rs,  o);
        }
        if (lane == 0) {
            const float invDen = (t == 1) ? 1.0f : 1.0f / (KC * rs);
            float U  = fmaf(acc, invDen, iext);
            float u2 = 0.2f * U;
            float sv = u2 * u2;
            stcg64(&g_tok[t][row],
                   ((unsigned long long)(run + 1u) << 32) |
                   (unsigned long long)__float_as_uint(sv));
            if (t == ITERS) out[row] = U;    // U_14
        }
    }
}

__global__ void __launch_bounds__(TPB, 2)
step_kernel(const float* __restrict__ net_in,
            const float* __restrict__ J,
            float* __restrict__ out,
            int t)
{
    step_body(net_in, J, out, t, NBLK);
}

// Step 14: 149 CTAs — 148 workers + 1 collector (recSum_14, r_14).
__global__ void __launch_bounds__(TPB, 2)
step14_kernel(const float* __restrict__ net_in,
              const float* __restrict__ J,
              float* __restrict__ out)
{
    if (blockIdx.x < NBLK) {
        step_body(net_in, J, out, ITERS, NBLK + 1);
        return;
    }

    __shared__ __align__(16) float s_sm[Nn];
    __shared__ float s_part[12];
    __shared__ unsigned s_run;
    const int tid  = threadIdx.x;
    const int lane = tid & 31;
    const int wid  = tid >> 5;

    if (tid == 0) s_run = atomicAdd(&g_cnt[ITERS], 1u) / (NBLK + 1);
    pdl_launch_dependents();
    __syncthreads();

    float loc = poll_scatter(ITERS, s_run + 1u, tid, s_sm);
    #pragma unroll
    for (int o = 16; o; o >>= 1) loc += __shfl_xor_sync(0xffffffffu, loc, o);
    if (lane == 0) s_part[wid] = loc;
    __syncthreads();
    float tot = 0.f;
    #pragma unroll
    for (int w = 0; w < 12; ++w) tot += s_part[w];
    const float recS = KC * tot;

    if (tid == 0) out[Nn] = recS;                        // recSum_14
    const int cnt = (tid < Nn - 4 * TPB) ? 5 : 4;
    #pragma unroll
    for (int k = 0; k < 5; ++k)                          // r_14
        if (k < cnt) out[Nn + 1 + tid + k * TPB] = s_sm[tid + k * TPB] / recS;
}

extern "C" void kernel_launch(void* const* d_in, const int* in_sizes, int n_in,
                              void* d_out, int out_size)
{
    const float* a = (const float*)d_in[0];
    const float* b = (const float*)d_in[1];
    const float* net_in = a;
    const float* J      = b;
    if (n_in >= 2 && in_sizes[0] > in_sizes[1]) { net_in = b; J = a; }
    float* out = (float*)d_out;

    cudaLaunchAttribute attr[1];
    attr[0].id = cudaLaunchAttributeProgrammaticStreamSerialization;
    attr[0].val.programmaticStreamSerializationAllowed = 1;

    cudaLaunchConfig_t cfg = {};
    cfg.gridDim  = dim3(NBLK, 1, 1);
    cfg.blockDim = dim3(TPB, 1, 1);
    cfg.dynamicSmemBytes = 0;
    cfg.stream = 0;            // legacy default stream (captured by harness)
    cfg.attrs = attr;
    cfg.numAttrs = 1;

    for (int t = 1; t <= ITERS - 1; ++t)
        cudaLaunchKernelEx(&cfg, step_kernel, net_in, J, out, t);

    cudaLaunchConfig_t cfg14 = cfg;
    cfg14.gridDim = dim3(NBLK + 1, 1, 1);
    cudaLaunchKernelEx(&cfg14, step14_kernel, net_in, J, out);
}

// round 14
// speedup vs baseline: 2.0292x; 2.0292x over previous
#include <cuda_runtime.h>
#include <cuda_fp16.h>

// CANN recurrent net: convert node + 14 PDL-chained steps + final node.
//   convert: g_Jh = fp16(J), rows padded 1680 -> 1792 halves
//   step t:  y = fp32dot(fp16 J row, s_{t-1});  U = y/recSum_{t-1} + Iext;
//            s_t = (0.2 U)^2   (recSum fused into the matvec, deterministic)
//   final:   recSum_14, r_14 = s_14/recSum_14
//
// Geometry: 148 CTAs x 384 threads, 1 warp = 1 row. J prefetch (fp16, 28 regs)
// issued before griddepcontrol.wait; gate opens after prefetch issue. Lower
// register count (~55) allows 3 CTAs/SM -> 2-deep successor prefetch overlap.
// Halving J bytes halves the per-step L2 bandwidth floor.

#define Nn     1680
#define NP     1792          // padded row length (14 * 128)
#define NBLK   148
#define TPB    384           // 12 warps
#define ITERS  14
#define KC     0.005f

__device__ __half g_Jh[Nn * NP];   // fp16 J, zero-padded rows (5.74 MB)
__device__ float  g_s[2][Nn];      // unnormalized s vectors, parity-buffered

__device__ __forceinline__ void pdl_wait() {
    asm volatile("griddepcontrol.wait;" ::: "memory");
}
__device__ __forceinline__ void pdl_launch_dependents() {
    asm volatile("griddepcontrol.launch_dependents;" ::: "memory");
}
__device__ __forceinline__ float4 ldcg4(const float4* p) {
    float4 v;
    asm volatile("ld.global.cg.v4.f32 {%0,%1,%2,%3}, [%4];"
                 : "=f"(v.x), "=f"(v.y), "=f"(v.z), "=f"(v.w) : "l"(p));
    return v;
}

// ---- convert node: J fp32 -> fp16 padded. No explicit gate: successor
// launches at grid completion (full flush), so g_Jh is globally visible. ----
__global__ void __launch_bounds__(TPB)
convert_kernel(const float* __restrict__ J)
{
    __half2* dst = reinterpret_cast<__half2*>(g_Jh);
    const int total = Nn * (NP / 2);              // half2 slots
    for (int idx = blockIdx.x * TPB + threadIdx.x; idx < total;
         idx += gridDim.x * TPB) {
        const int row = idx / (NP / 2);
        const int c2  = idx % (NP / 2);
        const int c0  = 2 * c2;
        __half2 v;
        if (c0 < Nn) {                            // Nn even: both cols in-range
            const float* src = J + (size_t)row * Nn + c0;
            v = __floats2half2_rn(src[0], src[1]);
        } else {
            v = __floats2half2_rn(0.f, 0.f);
        }
        dst[idx] = v;
    }
}

__global__ void __launch_bounds__(TPB, 2)
step_kernel(const float* __restrict__ net_in,
            const float* __restrict__ J,      // unused (kept for uniform sig)
            float* __restrict__ out,
            int t)
{
    __shared__ __align__(16) float s_sm[NP];   // padded s vector (7168 B)

    const int tid  = threadIdx.x;
    const int lane = tid & 31;
    const int wid  = tid >> 5;
    const int row  = wid * NBLK + (int)blockIdx.x;  // 12*148 = 1776 >= 1680
    const bool active = (row < Nn);

    // zero the pad once (written before any barrier, read only after)
    if (tid < NP - Nn) s_sm[Nn + tid] = 0.f;

    // ---- prefetch (runs pre-wait; g_Jh valid: convert node fully precedes
    //      the first step, later steps are even further downstream) ----
    uint2 Jr[14];                                   // 14 x 4 halves = 56/row
    float iext = 0.f;
    if (active) {
        iext = __ldg(&net_in[row]);
        const uint2* Jp = reinterpret_cast<const uint2*>(g_Jh + (size_t)row * NP);
        #pragma unroll
        for (int j = 0; j < 14; ++j) Jr[j] = __ldg(&Jp[j * 32 + lane]);
    }

    if (t == 1) {   // launch-constant input: stage before the wait
        const float4* r4 = reinterpret_cast<const float4*>(net_in + Nn);
        #pragma unroll
        for (int k = 0; k < 2; ++k) {
            int i = tid + k * TPB;
            if (i < Nn / 4) reinterpret_cast<float4*>(s_sm)[i] = __ldg(&r4[i]);
        }
    }

    pdl_launch_dependents();   // gate opens after our loads are queued
    pdl_wait();                // predecessor's g_s writes now visible

    if (t != 1) {
        const float4* sp = reinterpret_cast<const float4*>(g_s[(t - 1) & 1]);
        #pragma unroll
        for (int k = 0; k < 2; ++k) {
            int i = tid + k * TPB;
            if (i < Nn / 4) reinterpret_cast<float4*>(s_sm)[i] = ldcg4(&sp[i]);
        }
    }
    __syncthreads();

    // ---- matvec (fp16 J regs -> fp32 FMA) with fused recSum ----
    if (active) {
        const float4* s4 = reinterpret_cast<const float4*>(s_sm);
        float a0 = 0.f, a1 = 0.f, rs = 0.f;
        #pragma unroll
        for (int j = 0; j < 14; ++j) {
            float4 b = s4[j * 32 + lane];
            rs += (b.x + b.y) + (b.z + b.w);
            const float2 f0 = __half22float2(*reinterpret_cast<__half2*>(&Jr[j].x));
            const float2 f1 = __half22float2(*reinterpret_cast<__half2*>(&Jr[j].y));
            if (j & 1) {
                a1 = fmaf(f0.x, b.x, a1); a1 = fmaf(f0.y, b.y, a1);
                a1 = fmaf(f1.x, b.z, a1); a1 = fmaf(f1.y, b.w, a1);
            } else {
                a0 = fmaf(f0.x, b.x, a0); a0 = fmaf(f0.y, b.y, a0);
                a0 = fmaf(f1.x, b.z, a0); a0 = fmaf(f1.y, b.w, a0);
            }
        }
        float acc = a0 + a1;
        #pragma unroll
        for (int o = 16; o; o >>= 1) {
            acc += __shfl_xor_sync(0xffffffffu, acc, o);
            rs  += __shfl_xor_sync(0xffffffffu, rs,  o);
        }
        if (lane == 0) {
            const float invDen = (t == 1) ? 1.0f : 1.0f / (KC * rs);
            float U  = fmaf(acc, invDen, iext);
            float u2 = 0.2f * U;
            float sv = u2 * u2;
            g_s[t & 1][row] = sv;
            if (t == ITERS) out[row] = U;    // U_14
        }
    }
}

__global__ void __launch_bounds__(448)
final_kernel(float* __restrict__ out)
{
    __shared__ float s_part[14];
    const int tid = threadIdx.x, lane = tid & 31, wid = tid >> 5;

    pdl_wait();

    const float4* s4 = reinterpret_cast<const float4*>(g_s[ITERS & 1]);
    const bool has = tid < Nn / 4;     // 420 of 448 threads carry a float4
    float4 a = make_float4(0.f, 0.f, 0.f, 0.f);
    if (has) a = ldcg4(&s4[tid]);
    float v = (a.x + a.y) + (a.z + a.w);
    #pragma unroll
    for (int o = 16; o; o >>= 1) v += __shfl_xor_sync(0xffffffffu, v, o);
    if (lane == 0) s_part[wid] = v;
    __syncthreads();
    float rsum = 0.f;
    #pragma unroll
    for (int w = 0; w < 14; ++w) rsum += s_part[w];
    const float recS = KC * rsum;

    if (tid == 0) out[Nn] = recS;                       // recSum_14
    if (has) {                                          // r_14
        out[Nn + 1 + 4 * tid + 0] = a.x / recS;
        out[Nn + 1 + 4 * tid + 1] = a.y / recS;
        out[Nn + 1 + 4 * tid + 2] = a.z / recS;
        out[Nn + 1 + 4 * tid + 3] = a.w / recS;
    }
}

extern "C" void kernel_launch(void* const* d_in, const int* in_sizes, int n_in,
                              void* d_out, int out_size)
{
    const float* a = (const float*)d_in[0];
    const float* b = (const float*)d_in[1];
    const float* net_in = a;
    const float* J      = b;
    if (n_in >= 2 && in_sizes[0] > in_sizes[1]) { net_in = b; J = a; }
    float* out = (float*)d_out;

    cudaLaunchAttribute attr[1];
    attr[0].id = cudaLaunchAttributeProgrammaticStreamSerialization;
    attr[0].val.programmaticStreamSerializationAllowed = 1;

    cudaLaunchConfig_t cfg = {};
    cfg.gridDim  = dim3(NBLK, 1, 1);
    cfg.blockDim = dim3(TPB, 1, 1);
    cfg.dynamicSmemBytes = 0;
    cfg.stream = 0;            // legacy default stream (captured by harness)
    cfg.attrs = attr;
    cfg.numAttrs = 1;

    // convert node: no launch_dependents inside -> successor launches at
    // grid completion (full flush), guaranteeing g_Jh visibility.
    cudaLaunchKernelEx(&cfg, convert_kernel, J);

    for (int t = 1; t <= ITERS; ++t)
        cudaLaunchKernelEx(&cfg, step_kernel, net_in, J, out, t);

    cudaLaunchConfig_t cfgF = cfg;
    cfgF.gridDim  = dim3(1, 1, 1);
    cfgF.blockDim = dim3(448, 1, 1);
    cudaLaunchKernelEx(&cfgF, final_kernel, out);
}